// round 11
// baseline (speedup 1.0000x reference)
#include <cuda_runtime.h>
#include <cuda_fp16.h>
#include <cstdint>

#define DIMN 2048
#define BTOK 16384
#define HOFF 4096
#define QKV3 6144

#define MT 128                      /* CTA tile M */
#define NTCTA 256                   /* CTA tile N */
#define KT 64                       /* fp16 elems per chunk = 128 B/row */
#define NSTG 4
#define NTHR 256
#define ABYTES (MT * KT * 2)        /* 16384 */
#define BBYTES (NTCTA * KT * 2)     /* 32768 */
#define STGB (ABYTES + BBYTES)      /* 49152 */
#define SMEM_DYN (NSTG * STGB)      /* 196608 */

// Scratch (allocation-free per harness rules)
__device__ __half g_XH[(size_t)BTOK * DIMN];   // fp16+perm(x)       64 MB
__device__ __half g_WPH[(size_t)DIMN * DIMN];  // fp16+perm(Wp^T)     8 MB
__device__ __half g_WVH[(size_t)DIMN * DIMN];  // fp16+perm(Wv)       8 MB
__device__ __half g_WTH[(size_t)DIMN * DIMN];  // fp16+perm(Wv@Wp)^T  8 MB
__device__ float  g_BP[32 * DIMN];             // bias partials
__device__ float  g_CB[DIMN];                  // fused bias

// ---------------- helpers ----------------
__device__ __forceinline__ uint32_t smem_u32(const void* p) {
    uint32_t a;
    asm("{ .reg .u64 t; cvta.to.shared.u64 t, %1; cvt.u32.u64 %0, t; }"
        : "=r"(a) : "l"(p));
    return a;
}
__device__ __forceinline__ void cp16(uint32_t dst, const void* src) {
    asm volatile("cp.async.cg.shared.global [%0], [%1], 16;"
                 :: "r"(dst), "l"(src) : "memory");
}
#define CP_COMMIT() asm volatile("cp.async.commit_group;" ::: "memory")
#define CP_WAIT2()  asm volatile("cp.async.wait_group 2;" ::: "memory")

__device__ __forceinline__ uint4 lds128(uint32_t a) {
    uint4 v;
    asm volatile("ld.shared.v4.b32 {%0,%1,%2,%3}, [%4];"
                 : "=r"(v.x), "=r"(v.y), "=r"(v.z), "=r"(v.w) : "r"(a));
    return v;
}
__device__ __forceinline__ void mma_f16(float* d,
                                        uint32_t a0, uint32_t a1, uint32_t a2, uint32_t a3,
                                        uint32_t b0, uint32_t b1) {
    asm volatile(
        "mma.sync.aligned.m16n8k16.row.col.f32.f16.f16.f32 "
        "{%0,%1,%2,%3}, {%4,%5,%6,%7}, {%8,%9}, {%0,%1,%2,%3};"
        : "+f"(d[0]), "+f"(d[1]), "+f"(d[2]), "+f"(d[3])
        : "r"(a0), "r"(a1), "r"(a2), "r"(a3), "r"(b0), "r"(b1));
}

// ---------------- prepass kernels ----------------
// dst row-major fp16, each 32-elem k-group permuted at b32 granularity:
// phys b32 (4t+j) <- logical b32 (t+4j).
__global__ void pack_h_kernel(const float* __restrict__ src,
                              __half* __restrict__ dst,
                              int src_ld, int rows) {
    const int gpr = DIMN / 32;  // 64 groups per row
    size_t total = (size_t)rows * gpr;
    for (size_t g = (size_t)blockIdx.x * blockDim.x + threadIdx.x; g < total;
         g += (size_t)gridDim.x * blockDim.x) {
        size_t r = g / gpr;
        int c = (int)(g % gpr);
        const float* s = src + r * src_ld + c * 32;
        float f[32];
#pragma unroll
        for (int q = 0; q < 8; ++q) {
            float4 v = reinterpret_cast<const float4*>(s)[q];
            f[q * 4 + 0] = v.x; f[q * 4 + 1] = v.y;
            f[q * 4 + 2] = v.z; f[q * 4 + 3] = v.w;
        }
        __half2 d[16];
#pragma unroll
        for (int p = 0; p < 16; ++p) {
            int t = p >> 2, j = p & 3;
            int l = t + 4 * j;
            d[p] = __floats2half2_rn(f[2 * l], f[2 * l + 1]);
        }
        uint4* dd = reinterpret_cast<uint4*>(dst + r * DIMN + c * 32);
        const uint4* ds = reinterpret_cast<const uint4*>(d);
        dd[0] = ds[0]; dd[1] = ds[1]; dd[2] = ds[2]; dd[3] = ds[3];
    }
}

// WPH[j, permphys(h)] = fp16(w_proj[h, j])
__global__ void transpose_h_kernel(const float* __restrict__ in,
                                   __half* __restrict__ out, int n) {
    __shared__ float t[32][33];
    int x = blockIdx.x * 32 + threadIdx.x;
    int y0 = blockIdx.y * 32;
    for (int i = threadIdx.y; i < 32; i += 8)
        t[i][threadIdx.x] = in[(size_t)(y0 + i) * n + x];
    __syncthreads();
    int xo = blockIdx.y * 32 + threadIdx.x;
    int l = (xo & 31) >> 1;
    int e = xo & 1;
    int tt = l & 3, j = l >> 2;
    int xo_phys = (xo & ~31) | (((4 * tt + j) << 1) | e);
    int yo0 = blockIdx.x * 32;
    for (int i = threadIdx.y; i < 32; i += 8)
        out[(size_t)(yo0 + i) * n + xo_phys] = __float2half_rn(t[threadIdx.x][i]);
}

__global__ void bias_p1_kernel(const float* __restrict__ b_qkv,
                               const float* __restrict__ w_proj,
                               float* __restrict__ bp) {
    int j = blockIdx.x * blockDim.x + threadIdx.x;
    int h0 = blockIdx.y * 64;
    float acc = 0.0f;
#pragma unroll 8
    for (int h = h0; h < h0 + 64; ++h)
        acc += b_qkv[HOFF + h] * w_proj[(size_t)h * DIMN + j];
    bp[(size_t)blockIdx.y * DIMN + j] = acc;
}
__global__ void bias_p2_kernel(const float* __restrict__ bp,
                               const float* __restrict__ b_proj,
                               float* __restrict__ cb) {
    int j = blockIdx.x * blockDim.x + threadIdx.x;
    float acc = b_proj[j];
#pragma unroll
    for (int p = 0; p < 32; ++p) acc += bp[(size_t)p * DIMN + j];
    cb[j] = acc;
}

// ---------------- fp16 mma.sync GEMM ----------------
// out[m,n] = sum_k A[m,k]*B[n,k] (+bias[n]); A,B fp16, 32-group permuted.
// CTA 128x256, 8 warps of 64x64, KT=64 chunks, 4-stage cp.async ring.
// Inner loop software-pipelined: B-fragments prefetched one step ahead.
// If outh != nullptr, epilogue writes fp16 + perm (for weight precompute).
__device__ __forceinline__ void fill_stage(uint32_t sa,
                                           const __half* __restrict__ A,
                                           const __half* __restrict__ B,
                                           int m0, int n0, int k0,
                                           int lda, int ldb, int tid) {
    const __half* ab = A + (size_t)m0 * lda + k0;
#pragma unroll
    for (int i = tid; i < MT * 8; i += NTHR) {       // 1024 x 16B
        int row = i >> 3, cw = i & 7;
        cp16(sa + row * 128 + ((cw ^ ((row & 1) << 2)) << 4),
             ab + (size_t)row * lda + cw * 8);
    }
    const __half* bb = B + (size_t)n0 * ldb + k0;
    uint32_t sbb = sa + ABYTES;
#pragma unroll
    for (int i = tid; i < NTCTA * 8; i += NTHR) {    // 2048 x 16B
        int row = i >> 3, cw = i & 7;
        cp16(sbb + row * 128 + ((cw ^ ((row & 1) << 2)) << 4),
             bb + (size_t)row * ldb + cw * 8);
    }
}

__device__ __forceinline__ uint32_t frag_addr(uint32_t base, int row, int g, int tig) {
    return base + row * 128 + ((((g << 2) | tig) ^ ((row & 1) << 2)) << 4);
}

__global__ void __launch_bounds__(NTHR, 1)
gemm_f16_kernel(const __half* __restrict__ A, const __half* __restrict__ B,
                float* __restrict__ out, __half* __restrict__ outh,
                const float* __restrict__ bias,
                int K, int lda, int ldb, int ldo) {
    extern __shared__ __align__(16) char smem[];
    const uint32_t sb = smem_u32(smem);

    const int tid = threadIdx.x;
    const int wid = tid >> 5;
    const int lane = tid & 31;
    const int gid = lane >> 2;        // 0..7
    const int tig = lane & 3;         // 0..3
    const int m0 = blockIdx.y * MT;
    const int n0 = blockIdx.x * NTCTA;
    const int moff = (wid & 1) * 64;  // 2 m-warps
    const int noff = (wid >> 1) * 64; // 4 n-warps

    float acc[4][8][4];
#pragma unroll
    for (int mt = 0; mt < 4; ++mt)
#pragma unroll
        for (int nt = 0; nt < 8; ++nt)
#pragma unroll
            for (int r = 0; r < 4; ++r) acc[mt][nt][r] = 0.0f;

    const int niter = K / KT;   // 32

    fill_stage(sb + 0 * STGB, A, B, m0, n0, 0 * KT, lda, ldb, tid); CP_COMMIT();
    fill_stage(sb + 1 * STGB, A, B, m0, n0, 1 * KT, lda, ldb, tid); CP_COMMIT();
    fill_stage(sb + 2 * STGB, A, B, m0, n0, 2 * KT, lda, ldb, tid); CP_COMMIT();

    int s = 0;
    for (int it = 0; it < niter; ++it) {
        CP_WAIT2();                  // stage `it` resident
        __syncthreads();             // all warps done with the stage being refilled

        const int c = it + 3;
        if (c < niter) {
            int sf = s + 3; if (sf >= NSTG) sf -= NSTG;
            fill_stage(sb + sf * STGB, A, B, m0, n0, c * KT, lda, ldb, tid);
        }
        CP_COMMIT();                 // uniform group count per iter

        const uint32_t sA = sb + s * STGB;
        const uint32_t sB = sA + ABYTES;

#pragma unroll
        for (int g = 0; g < 2; ++g) {    // each group covers two k16 steps
            uint4 a0[4], a1[4];
#pragma unroll
            for (int mt = 0; mt < 4; ++mt) {
                int r0 = moff + mt * 16 + gid;
                a0[mt] = lds128(frag_addr(sA, r0, g, tig));
                a1[mt] = lds128(frag_addr(sA, r0 + 8, g, tig));
            }
            // pipelined B-fragment stream: prefetch one nt ahead
            uint4 bfc = lds128(frag_addr(sB, noff + gid, g, tig));
#pragma unroll
            for (int nt = 0; nt < 8; ++nt) {
                uint4 bfn;
                if (nt < 7)
                    bfn = lds128(frag_addr(sB, noff + (nt + 1) * 8 + gid, g, tig));
#pragma unroll
                for (int mt = 0; mt < 4; ++mt)
                    mma_f16(acc[mt][nt], a0[mt].x, a1[mt].x, a0[mt].y, a1[mt].y,
                            bfc.x, bfc.y);
#pragma unroll
                for (int mt = 0; mt < 4; ++mt)
                    mma_f16(acc[mt][nt], a0[mt].z, a1[mt].z, a0[mt].w, a1[mt].w,
                            bfc.z, bfc.w);
                bfc = bfn;
            }
        }
        if (++s == NSTG) s = 0;
    }

    // ---------------- epilogue ----------------
    if (outh) {
        // fp16 + perm pack directly (weight precompute path); no bias.
#pragma unroll
        for (int mt = 0; mt < 4; ++mt) {
            const int r0 = m0 + moff + mt * 16 + gid;
#pragma unroll
            for (int nt = 0; nt < 8; ++nt) {
                const int col = n0 + noff + nt * 8 + tig * 2;
                const int gbase = col & ~31;
                const int l = (col & 31) >> 1;          // logical b32 in group
                const int p = 4 * (l & 3) + (l >> 2);   // phys b32
                const int pc = gbase + p * 2;
                __half2 h0 = __floats2half2_rn(acc[mt][nt][0], acc[mt][nt][1]);
                __half2 h1 = __floats2half2_rn(acc[mt][nt][2], acc[mt][nt][3]);
                *reinterpret_cast<__half2*>(outh + (size_t)r0 * ldo + pc) = h0;
                *reinterpret_cast<__half2*>(outh + (size_t)(r0 + 8) * ldo + pc) = h1;
            }
        }
        return;
    }

    float2 bb2[8];
#pragma unroll
    for (int nt = 0; nt < 8; ++nt) {
        if (bias) {
            bb2[nt] = *reinterpret_cast<const float2*>(
                bias + n0 + noff + nt * 8 + tig * 2);
        } else {
            bb2[nt].x = 0.0f; bb2[nt].y = 0.0f;
        }
    }
#pragma unroll
    for (int mt = 0; mt < 4; ++mt) {
        const int r0 = m0 + moff + mt * 16 + gid;
#pragma unroll
        for (int nt = 0; nt < 8; ++nt) {
            const int col = n0 + noff + nt * 8 + tig * 2;
            float2 v0, v1;
            v0.x = acc[mt][nt][0] + bb2[nt].x;
            v0.y = acc[mt][nt][1] + bb2[nt].y;
            v1.x = acc[mt][nt][2] + bb2[nt].x;
            v1.y = acc[mt][nt][3] + bb2[nt].y;
            *reinterpret_cast<float2*>(out + (size_t)r0 * ldo + col) = v0;
            *reinterpret_cast<float2*>(out + (size_t)(r0 + 8) * ldo + col) = v1;
        }
    }
}

// ---------------- host ----------------
extern "C" void kernel_launch(void* const* d_in, const int* in_sizes, int n_in,
                              void* d_out, int out_size) {
    (void)in_sizes; (void)n_in; (void)out_size;
    const float* x     = (const float*)d_in[0];
    const float* wqkv  = (const float*)d_in[1];
    const float* bqkv  = (const float*)d_in[2];
    const float* wproj = (const float*)d_in[3];
    const float* bproj = (const float*)d_in[4];
    float* out = (float*)d_out;

    __half *XH, *WPH, *WVH, *WTH;
    float *BP, *CB;
    cudaGetSymbolAddress((void**)&XH,  g_XH);
    cudaGetSymbolAddress((void**)&WPH, g_WPH);
    cudaGetSymbolAddress((void**)&WVH, g_WVH);
    cudaGetSymbolAddress((void**)&WTH, g_WTH);
    cudaGetSymbolAddress((void**)&BP,  g_BP);
    cudaGetSymbolAddress((void**)&CB,  g_CB);

    cudaFuncSetAttribute(gemm_f16_kernel,
                         cudaFuncAttributeMaxDynamicSharedMemorySize, SMEM_DYN);

    // Prepasses: pack to fp16+perm; fold bias (two-phase, deterministic)
    pack_h_kernel<<<4096, 256>>>(x, XH, DIMN, BTOK);
    transpose_h_kernel<<<dim3(64, 64), dim3(32, 8)>>>(wproj, WPH, DIMN);
    pack_h_kernel<<<512, 256>>>(wqkv + HOFF, WVH, QKV3, DIMN);
    bias_p1_kernel<<<dim3(8, 32), 256>>>(bqkv, wproj, BP);
    bias_p2_kernel<<<8, 256>>>(BP, bproj, CB);

    // Precompute: WTH[j, perm(k)] = fp16( sum_h WPH[j,h] * WVH[k,h] )
    gemm_f16_kernel<<<dim3(DIMN / NTCTA, DIMN / MT), NTHR, SMEM_DYN>>>(
        WPH, WVH, nullptr, WTH, nullptr, DIMN, DIMN, DIMN, DIMN);

    // out[b,j] = sum_k XH[b,k] * WTH[j,k] + CB[j]
    gemm_f16_kernel<<<dim3(DIMN / NTCTA, BTOK / MT), NTHR, SMEM_DYN>>>(
        XH, WTH, out, nullptr, CB, DIMN, DIMN, DIMN, DIMN);
}

// round 12
// speedup vs baseline: 1.1136x; 1.1136x over previous
#include <cuda_runtime.h>
#include <cuda_fp16.h>
#include <cstdint>

#define DIMN 2048
#define BTOK 16384
#define HOFF 4096
#define QKV3 6144

#define MT 128                      /* CTA tile M */
#define NTCTA 256                   /* CTA tile N */
#define KT 128                      /* fp16 elems per chunk = 256 B/row */
#define NSTG 2
#define NTHR 256
#define ABYTES (MT * KT * 2)        /* 32768 */
#define BBYTES (NTCTA * KT * 2)     /* 65536 */
#define STGB (ABYTES + BBYTES)      /* 98304 */
#define SMEM_DYN (NSTG * STGB)      /* 196608 */

// Scratch (allocation-free per harness rules)
__device__ __half g_XH[(size_t)BTOK * DIMN];   // fp16+perm(x)       64 MB
__device__ __half g_WPH[(size_t)DIMN * DIMN];  // fp16+perm(Wp^T)     8 MB
__device__ __half g_WVH[(size_t)DIMN * DIMN];  // fp16+perm(Wv)       8 MB
__device__ __half g_WTH[(size_t)DIMN * DIMN];  // fp16+perm(Wv@Wp)^T  8 MB
__device__ float  g_BP[32 * DIMN];             // bias partials
__device__ float  g_CB[DIMN];                  // fused bias

// ---------------- helpers ----------------
__device__ __forceinline__ uint32_t smem_u32(const void* p) {
    uint32_t a;
    asm("{ .reg .u64 t; cvta.to.shared.u64 t, %1; cvt.u32.u64 %0, t; }"
        : "=r"(a) : "l"(p));
    return a;
}
__device__ __forceinline__ void cp16(uint32_t dst, const void* src) {
    asm volatile("cp.async.cg.shared.global [%0], [%1], 16;"
                 :: "r"(dst), "l"(src) : "memory");
}
#define CP_COMMIT() asm volatile("cp.async.commit_group;" ::: "memory")
#define CP_WAIT0()  asm volatile("cp.async.wait_group 0;" ::: "memory")

__device__ __forceinline__ uint4 lds128(uint32_t a) {
    uint4 v;
    asm volatile("ld.shared.v4.b32 {%0,%1,%2,%3}, [%4];"
                 : "=r"(v.x), "=r"(v.y), "=r"(v.z), "=r"(v.w) : "r"(a));
    return v;
}
__device__ __forceinline__ void mma_f16(float* d,
                                        uint32_t a0, uint32_t a1, uint32_t a2, uint32_t a3,
                                        uint32_t b0, uint32_t b1) {
    asm volatile(
        "mma.sync.aligned.m16n8k16.row.col.f32.f16.f16.f32 "
        "{%0,%1,%2,%3}, {%4,%5,%6,%7}, {%8,%9}, {%0,%1,%2,%3};"
        : "+f"(d[0]), "+f"(d[1]), "+f"(d[2]), "+f"(d[3])
        : "r"(a0), "r"(a1), "r"(a2), "r"(a3), "r"(b0), "r"(b1));
}

// ---------------- prepass kernels ----------------
// dst row-major fp16, each 32-elem k-group permuted at b32 granularity:
// phys b32 (4t+j) <- logical b32 (t+4j).
__global__ void pack_h_kernel(const float* __restrict__ src,
                              __half* __restrict__ dst,
                              int src_ld, int rows) {
    const int gpr = DIMN / 32;  // 64 groups per row
    size_t total = (size_t)rows * gpr;
    for (size_t g = (size_t)blockIdx.x * blockDim.x + threadIdx.x; g < total;
         g += (size_t)gridDim.x * blockDim.x) {
        size_t r = g / gpr;
        int c = (int)(g % gpr);
        const float* s = src + r * src_ld + c * 32;
        float f[32];
#pragma unroll
        for (int q = 0; q < 8; ++q) {
            float4 v = reinterpret_cast<const float4*>(s)[q];
            f[q * 4 + 0] = v.x; f[q * 4 + 1] = v.y;
            f[q * 4 + 2] = v.z; f[q * 4 + 3] = v.w;
        }
        __half2 d[16];
#pragma unroll
        for (int p = 0; p < 16; ++p) {
            int t = p >> 2, j = p & 3;
            int l = t + 4 * j;
            d[p] = __floats2half2_rn(f[2 * l], f[2 * l + 1]);
        }
        uint4* dd = reinterpret_cast<uint4*>(dst + r * DIMN + c * 32);
        const uint4* ds = reinterpret_cast<const uint4*>(d);
        dd[0] = ds[0]; dd[1] = ds[1]; dd[2] = ds[2]; dd[3] = ds[3];
    }
}

// WPH[j, permphys(h)] = fp16(w_proj[h, j])
__global__ void transpose_h_kernel(const float* __restrict__ in,
                                   __half* __restrict__ out, int n) {
    __shared__ float t[32][33];
    int x = blockIdx.x * 32 + threadIdx.x;
    int y0 = blockIdx.y * 32;
    for (int i = threadIdx.y; i < 32; i += 8)
        t[i][threadIdx.x] = in[(size_t)(y0 + i) * n + x];
    __syncthreads();
    int xo = blockIdx.y * 32 + threadIdx.x;
    int l = (xo & 31) >> 1;
    int e = xo & 1;
    int tt = l & 3, j = l >> 2;
    int xo_phys = (xo & ~31) | (((4 * tt + j) << 1) | e);
    int yo0 = blockIdx.x * 32;
    for (int i = threadIdx.y; i < 32; i += 8)
        out[(size_t)(yo0 + i) * n + xo_phys] = __float2half_rn(t[threadIdx.x][i]);
}

__global__ void bias_p1_kernel(const float* __restrict__ b_qkv,
                               const float* __restrict__ w_proj,
                               float* __restrict__ bp) {
    int j = blockIdx.x * blockDim.x + threadIdx.x;
    int h0 = blockIdx.y * 64;
    float acc = 0.0f;
#pragma unroll 8
    for (int h = h0; h < h0 + 64; ++h)
        acc += b_qkv[HOFF + h] * w_proj[(size_t)h * DIMN + j];
    bp[(size_t)blockIdx.y * DIMN + j] = acc;
}
__global__ void bias_p2_kernel(const float* __restrict__ bp,
                               const float* __restrict__ b_proj,
                               float* __restrict__ cb) {
    int j = blockIdx.x * blockDim.x + threadIdx.x;
    float acc = b_proj[j];
#pragma unroll
    for (int p = 0; p < 32; ++p) acc += bp[(size_t)p * DIMN + j];
    cb[j] = acc;
}

// ---------------- fp16 mma.sync GEMM ----------------
// out[m,n] = sum_k A[m,k]*B[n,k] (+bias[n]); A,B fp16, 32-group permuted.
// CTA 128x256, 8 warps of 64x64 (R8 loop body), KT=128 chunks, double buffer.
// If outh != nullptr, epilogue writes fp16 + perm (weight precompute path).
__device__ __forceinline__ void fill_stage(uint32_t sa,
                                           const __half* __restrict__ A,
                                           const __half* __restrict__ B,
                                           int m0, int n0, int k0,
                                           int lda, int ldb, int tid) {
    const __half* ab = A + (size_t)m0 * lda + k0;
#pragma unroll
    for (int i = tid; i < MT * 16; i += NTHR) {      // 2048 x 16B
        int row = i >> 4, cw = i & 15;
        cp16(sa + row * 256 + ((cw ^ ((row & 1) << 2)) << 4),
             ab + (size_t)row * lda + cw * 8);
    }
    const __half* bb = B + (size_t)n0 * ldb + k0;
    uint32_t sbb = sa + ABYTES;
#pragma unroll
    for (int i = tid; i < NTCTA * 16; i += NTHR) {   // 4096 x 16B
        int row = i >> 4, cw = i & 15;
        cp16(sbb + row * 256 + ((cw ^ ((row & 1) << 2)) << 4),
             bb + (size_t)row * ldb + cw * 8);
    }
}

__device__ __forceinline__ uint32_t frag_addr(uint32_t base, int row, int g, int tig) {
    return base + row * 256 + ((((g << 2) | tig) ^ ((row & 1) << 2)) << 4);
}

__global__ void __launch_bounds__(NTHR, 1)
gemm_f16_kernel(const __half* __restrict__ A, const __half* __restrict__ B,
                float* __restrict__ out, __half* __restrict__ outh,
                const float* __restrict__ bias,
                int K, int lda, int ldb, int ldo) {
    extern __shared__ __align__(16) char smem[];
    const uint32_t sb = smem_u32(smem);

    const int tid = threadIdx.x;
    const int wid = tid >> 5;
    const int lane = tid & 31;
    const int gid = lane >> 2;        // 0..7
    const int tig = lane & 3;         // 0..3
    const int m0 = blockIdx.y * MT;
    const int n0 = blockIdx.x * NTCTA;
    const int moff = (wid & 1) * 64;  // 2 m-warps
    const int noff = (wid >> 1) * 64; // 4 n-warps

    float acc[4][8][4];
#pragma unroll
    for (int mt = 0; mt < 4; ++mt)
#pragma unroll
        for (int nt = 0; nt < 8; ++nt)
#pragma unroll
            for (int r = 0; r < 4; ++r) acc[mt][nt][r] = 0.0f;

    const int niter = K / KT;   // 16

    fill_stage(sb, A, B, m0, n0, 0, lda, ldb, tid);
    CP_COMMIT();

    for (int it = 0; it < niter; ++it) {
        CP_WAIT0();                  // stage `it` resident (own fills)
        __syncthreads();             // visible to all; prev compute finished

        const int c = it + 1;
        if (c < niter)
            fill_stage(sb + (c & 1) * STGB, A, B, m0, n0, c * KT, lda, ldb, tid);
        CP_COMMIT();                 // uniform group count per iter

        const uint32_t sA = sb + (it & 1) * STGB;
        const uint32_t sB = sA + ABYTES;

#pragma unroll
        for (int g = 0; g < 4; ++g) {    // each group covers two k16 steps
            uint4 a0[4], a1[4];
#pragma unroll
            for (int mt = 0; mt < 4; ++mt) {
                int r0 = moff + mt * 16 + gid;
                a0[mt] = lds128(frag_addr(sA, r0, g, tig));
                a1[mt] = lds128(frag_addr(sA, r0 + 8, g, tig));
            }
            uint4 bf[8];
#pragma unroll
            for (int nt = 0; nt < 8; ++nt)
                bf[nt] = lds128(frag_addr(sB, noff + nt * 8 + gid, g, tig));

#pragma unroll
            for (int mt = 0; mt < 4; ++mt)
#pragma unroll
                for (int nt = 0; nt < 8; ++nt)
                    mma_f16(acc[mt][nt], a0[mt].x, a1[mt].x, a0[mt].y, a1[mt].y,
                            bf[nt].x, bf[nt].y);
#pragma unroll
            for (int mt = 0; mt < 4; ++mt)
#pragma unroll
                for (int nt = 0; nt < 8; ++nt)
                    mma_f16(acc[mt][nt], a0[mt].z, a1[mt].z, a0[mt].w, a1[mt].w,
                            bf[nt].z, bf[nt].w);
        }
    }

    // ---------------- epilogue ----------------
    if (outh) {
        // fp16 + perm pack directly (weight precompute path); no bias.
#pragma unroll
        for (int mt = 0; mt < 4; ++mt) {
            const int r0 = m0 + moff + mt * 16 + gid;
#pragma unroll
            for (int nt = 0; nt < 8; ++nt) {
                const int col = n0 + noff + nt * 8 + tig * 2;
                const int gbase = col & ~31;
                const int l = (col & 31) >> 1;          // logical b32 in group
                const int p = 4 * (l & 3) + (l >> 2);   // phys b32
                const int pc = gbase + p * 2;
                __half2 h0 = __floats2half2_rn(acc[mt][nt][0], acc[mt][nt][1]);
                __half2 h1 = __floats2half2_rn(acc[mt][nt][2], acc[mt][nt][3]);
                *reinterpret_cast<__half2*>(outh + (size_t)r0 * ldo + pc) = h0;
                *reinterpret_cast<__half2*>(outh + (size_t)(r0 + 8) * ldo + pc) = h1;
            }
        }
        return;
    }

    float2 bb2[8];
#pragma unroll
    for (int nt = 0; nt < 8; ++nt) {
        if (bias) {
            bb2[nt] = *reinterpret_cast<const float2*>(
                bias + n0 + noff + nt * 8 + tig * 2);
        } else {
            bb2[nt].x = 0.0f; bb2[nt].y = 0.0f;
        }
    }
#pragma unroll
    for (int mt = 0; mt < 4; ++mt) {
        const int r0 = m0 + moff + mt * 16 + gid;
#pragma unroll
        for (int nt = 0; nt < 8; ++nt) {
            const int col = n0 + noff + nt * 8 + tig * 2;
            float2 v0, v1;
            v0.x = acc[mt][nt][0] + bb2[nt].x;
            v0.y = acc[mt][nt][1] + bb2[nt].y;
            v1.x = acc[mt][nt][2] + bb2[nt].x;
            v1.y = acc[mt][nt][3] + bb2[nt].y;
            *reinterpret_cast<float2*>(out + (size_t)r0 * ldo + col) = v0;
            *reinterpret_cast<float2*>(out + (size_t)(r0 + 8) * ldo + col) = v1;
        }
    }
}

// ---------------- host ----------------
extern "C" void kernel_launch(void* const* d_in, const int* in_sizes, int n_in,
                              void* d_out, int out_size) {
    (void)in_sizes; (void)n_in; (void)out_size;
    const float* x     = (const float*)d_in[0];
    const float* wqkv  = (const float*)d_in[1];
    const float* bqkv  = (const float*)d_in[2];
    const float* wproj = (const float*)d_in[3];
    const float* bproj = (const float*)d_in[4];
    float* out = (float*)d_out;

    __half *XH, *WPH, *WVH, *WTH;
    float *BP, *CB;
    cudaGetSymbolAddress((void**)&XH,  g_XH);
    cudaGetSymbolAddress((void**)&WPH, g_WPH);
    cudaGetSymbolAddress((void**)&WVH, g_WVH);
    cudaGetSymbolAddress((void**)&WTH, g_WTH);
    cudaGetSymbolAddress((void**)&BP,  g_BP);
    cudaGetSymbolAddress((void**)&CB,  g_CB);

    cudaFuncSetAttribute(gemm_f16_kernel,
                         cudaFuncAttributeMaxDynamicSharedMemorySize, SMEM_DYN);

    // Prepasses: pack to fp16+perm; fold bias (two-phase, deterministic)
    pack_h_kernel<<<4096, 256>>>(x, XH, DIMN, BTOK);
    transpose_h_kernel<<<dim3(64, 64), dim3(32, 8)>>>(wproj, WPH, DIMN);
    pack_h_kernel<<<512, 256>>>(wqkv + HOFF, WVH, QKV3, DIMN);
    bias_p1_kernel<<<dim3(8, 32), 256>>>(bqkv, wproj, BP);
    bias_p2_kernel<<<8, 256>>>(BP, bproj, CB);

    // Precompute: WTH[j, perm(k)] = fp16( sum_h WPH[j,h] * WVH[k,h] )
    gemm_f16_kernel<<<dim3(DIMN / NTCTA, DIMN / MT), NTHR, SMEM_DYN>>>(
        WPH, WVH, nullptr, WTH, nullptr, DIMN, DIMN, DIMN, DIMN);

    // out[b,j] = sum_k XH[b,k] * WTH[j,k] + CB[j]
    gemm_f16_kernel<<<dim3(DIMN / NTCTA, BTOK / MT), NTHR, SMEM_DYN>>>(
        XH, WTH, out, nullptr, CB, DIMN, DIMN, DIMN, DIMN);
}